// round 4
// baseline (speedup 1.0000x reference)
#include <cuda_runtime.h>
#include <cuda_bf16.h>
#include <cstdint>

// Problem constants
#define B_  32
#define T_  4096
#define M_  256     // K dim of GEMM1
#define L_  128     // hidden (cols of GEMM1)

// Tiling
#define PAIRS     64            // (b,t) pairs per CTA
#define ROWS      128           // 2*PAIRS MMA rows (h1 rows 0..63, h2 rows 64..127)
#define NTHREADS  512           // warps 0-7 consumers, 8-15 producers
#define KCHUNK    64
#define NCHUNKS   (M_ / KCHUNK) // 4
#define HSTRIDE   72            // bf16 elems per H smem row (144B: 16B bank rotation)
#define VSTRIDE   264           // bf16 elems per V smem row (528B: 16B bank rotation)

// smem layout in bf16 elements
#define HHI_OFF   0                          // 2 buffers of ROWS*HSTRIDE
#define HLO_OFF   (2 * ROWS * HSTRIDE)       // 18432
#define VHI_OFF   (4 * ROWS * HSTRIDE)       // 36864
#define VLO_OFF   (VHI_OFF + L_ * VSTRIDE)   // 70656
#define BF16_TOT  (VLO_OFF + L_ * VSTRIDE)   // 104448 elems = 208896 B
#define SMEM_BYTES (BF16_TOT * 2 + ROWS * 4 + L_ * 4)   // 209920 B

// named barriers: 1+buf = full, 3+buf = empty, 5 = consumer-only V barrier
#define BAR_SYNC(id, cnt)   asm volatile("bar.sync %0, %1;"   :: "r"(id), "r"(cnt) : "memory")
#define BAR_ARRIVE(id, cnt) asm volatile("bar.arrive %0, %1;" :: "r"(id), "r"(cnt) : "memory")

__device__ __forceinline__ float fast_tanh(float x) {
    float e = __expf(2.0f * x);
    return 1.0f - __fdividef(2.0f, e + 1.0f);
}

__device__ __forceinline__ void split2(float a, float b, uint32_t& hi, uint32_t& lo) {
    __nv_bfloat16 ah = __float2bfloat16(a);
    __nv_bfloat16 bh = __float2bfloat16(b);
    __nv_bfloat162 hv; hv.x = ah; hv.y = bh;
    hi = *reinterpret_cast<uint32_t*>(&hv);
    __nv_bfloat162 lv;
    lv.x = __float2bfloat16(a - __bfloat162float(ah));
    lv.y = __float2bfloat16(b - __bfloat162float(bh));
    lo = *reinterpret_cast<uint32_t*>(&lv);
}

__device__ __forceinline__ void mma_bf16(float* c,
                                         const uint32_t* a,
                                         uint32_t b0, uint32_t b1) {
    asm("mma.sync.aligned.m16n8k16.row.col.f32.bf16.bf16.f32 "
        "{%0,%1,%2,%3}, {%4,%5,%6,%7}, {%8,%9}, {%0,%1,%2,%3};\n"
        : "+f"(c[0]), "+f"(c[1]), "+f"(c[2]), "+f"(c[3])
        : "r"(a[0]), "r"(a[1]), "r"(a[2]), "r"(a[3]), "r"(b0), "r"(b1));
}

__device__ __forceinline__ void ldsm4(uint32_t& r0, uint32_t& r1, uint32_t& r2, uint32_t& r3,
                                      uint32_t addr) {
    asm volatile("ldmatrix.sync.aligned.m8n8.x4.shared.b16 {%0,%1,%2,%3}, [%4];\n"
                 : "=r"(r0), "=r"(r1), "=r"(r2), "=r"(r3) : "r"(addr));
}

extern __shared__ char smem_raw[];

__global__ void __launch_bounds__(NTHREADS, 1)
topo_attn_kernel(const float* __restrict__ h1, const float* __restrict__ h2,
                 const float* __restrict__ w_tp, const float* __restrict__ v_tp,
                 float* __restrict__ out)
{
    __nv_bfloat16* sm = reinterpret_cast<__nv_bfloat16*>(smem_raw);
    __nv_bfloat16* Hhi = sm + HHI_OFF;
    __nv_bfloat16* Hlo = sm + HLO_OFF;
    __nv_bfloat16* Vhi = sm + VHI_OFF;
    __nv_bfloat16* Vlo = sm + VLO_OFF;
    float* score = reinterpret_cast<float*>(smem_raw + BF16_TOT * 2);
    float* ws    = score + ROWS;

    const int tid  = threadIdx.x;
    const int warp = tid >> 5;
    const int lane = tid & 31;
    const int pair0 = blockIdx.x * PAIRS;

    if (warp < 8) {
        // ================= CONSUMER =================
        if (tid < L_) ws[tid] = w_tp[tid];

        // one-time: load + split full V (128 x 256 fp32) into smem
        #pragma unroll 4
        for (int it = 0; it < 32; ++it) {
            int idx = it * 256 + tid;          // float4 index over 128*64
            int r   = idx >> 6;
            int c4  = idx & 63;
            float4 f = *reinterpret_cast<const float4*>(v_tp + (size_t)r * M_ + c4 * 4);
            uint2 hv, lv;
            split2(f.x, f.y, hv.x, lv.x);
            split2(f.z, f.w, hv.y, lv.y);
            *reinterpret_cast<uint2*>(Vhi + r * VSTRIDE + c4 * 4) = hv;
            *reinterpret_cast<uint2*>(Vlo + r * VSTRIDE + c4 * 4) = lv;
        }
        BAR_SYNC(5, 256);   // V + ws visible to all consumer warps

        const int g = lane >> 2;
        const int t = lane & 3;
        const int rb = warp * 16;

        // ldmatrix lane-address decomposition
        const int arow = rb + (lane & 7) + ((lane >> 3) & 1) * 8;
        const int acol = (lane >> 4) * 8;
        const int brow = (lane & 7) + ((lane >> 4) & 1) * 8;
        const int bcol = ((lane >> 3) & 1) * 8;

        const uint32_t a_hi0 = (uint32_t)__cvta_generic_to_shared(Hhi) + (arow * HSTRIDE + acol) * 2;
        const uint32_t a_lo0 = (uint32_t)__cvta_generic_to_shared(Hlo) + (arow * HSTRIDE + acol) * 2;
        const uint32_t b_hi0 = (uint32_t)__cvta_generic_to_shared(Vhi) + (brow * VSTRIDE + bcol) * 2;
        const uint32_t b_lo0 = (uint32_t)__cvta_generic_to_shared(Vlo) + (brow * VSTRIDE + bcol) * 2;

        float acc[16][4];
        #pragma unroll
        for (int n = 0; n < 16; ++n)
            #pragma unroll
            for (int q = 0; q < 4; ++q) acc[n][q] = 0.0f;

        for (int kc = 0; kc < NCHUNKS; ++kc) {
            const int buf = kc & 1;
            BAR_SYNC(1 + buf, NTHREADS);   // wait buffer full
            const uint32_t ah = a_hi0 + buf * (ROWS * HSTRIDE * 2);
            const uint32_t al = a_lo0 + buf * (ROWS * HSTRIDE * 2);
            #pragma unroll
            for (int ks = 0; ks < KCHUNK / 16; ++ks) {
                const int kk = ks * 16;
                uint32_t ahi[4], alo[4];
                ldsm4(ahi[0], ahi[1], ahi[2], ahi[3], ah + kk * 2);
                ldsm4(alo[0], alo[1], alo[2], alo[3], al + kk * 2);
                const uint32_t kb = (kc * KCHUNK + kk) * 2;
                #pragma unroll
                for (int p = 0; p < 8; ++p) {
                    uint32_t bh0, bh1, bh2, bh3, bl0, bl1, bl2, bl3;
                    ldsm4(bh0, bh1, bh2, bh3, b_hi0 + p * (16 * VSTRIDE * 2) + kb);
                    ldsm4(bl0, bl1, bl2, bl3, b_lo0 + p * (16 * VSTRIDE * 2) + kb);
                    mma_bf16(acc[2 * p],     ahi, bh0, bh1);
                    mma_bf16(acc[2 * p],     ahi, bl0, bl1);
                    mma_bf16(acc[2 * p],     alo, bh0, bh1);
                    mma_bf16(acc[2 * p + 1], ahi, bh2, bh3);
                    mma_bf16(acc[2 * p + 1], ahi, bl2, bl3);
                    mma_bf16(acc[2 * p + 1], alo, bh2, bh3);
                }
            }
            BAR_ARRIVE(3 + buf, NTHREADS); // buffer consumed
        }

        // epilogue: score[row] = sum_l w[l] * tanh(temp[row,l])
        float p0 = 0.f, p1 = 0.f;
        #pragma unroll
        for (int nt = 0; nt < 16; ++nt) {
            float w0 = ws[nt * 8 + 2 * t];
            float w1 = ws[nt * 8 + 2 * t + 1];
            p0 += w0 * fast_tanh(acc[nt][0]) + w1 * fast_tanh(acc[nt][1]);
            p1 += w0 * fast_tanh(acc[nt][2]) + w1 * fast_tanh(acc[nt][3]);
        }
        #pragma unroll
        for (int off = 1; off < 4; off <<= 1) {
            p0 += __shfl_xor_sync(0xffffffffu, p0, off);
            p1 += __shfl_xor_sync(0xffffffffu, p1, off);
        }
        if (t == 0) {
            score[rb + g]     = p0;
            score[rb + g + 8] = p1;
        }
    } else {
        // ================= PRODUCER =================
        const int p = tid - 256;
        for (int kc = 0; kc < NCHUNKS; ++kc) {
            const int buf = kc & 1;
            if (kc >= 2) BAR_SYNC(3 + buf, NTHREADS);   // wait buffer empty
            const int k0 = kc * KCHUNK;
            float4 f[8];
            #pragma unroll
            for (int it = 0; it < 8; ++it) {
                int idx = it * 256 + p;          // float4 idx over 128 rows * 16
                int r   = idx >> 4;
                int c4  = idx & 15;
                const float* src = (r < PAIRS)
                    ? (h1 + (size_t)(pair0 + r) * M_)
                    : (h2 + (size_t)(pair0 + r - PAIRS) * M_);
                f[it] = *reinterpret_cast<const float4*>(src + k0 + c4 * 4);
            }
            __nv_bfloat16* dh = Hhi + buf * (ROWS * HSTRIDE);
            __nv_bfloat16* dl = Hlo + buf * (ROWS * HSTRIDE);
            #pragma unroll
            for (int it = 0; it < 8; ++it) {
                int idx = it * 256 + p;
                int r   = idx >> 4;
                int c4  = idx & 15;
                uint2 hv, lv;
                split2(f[it].x, f[it].y, hv.x, lv.x);
                split2(f[it].z, f[it].w, hv.y, lv.y);
                *reinterpret_cast<uint2*>(dh + r * HSTRIDE + c4 * 4) = hv;
                *reinterpret_cast<uint2*>(dl + r * HSTRIDE + c4 * 4) = lv;
            }
            BAR_ARRIVE(1 + buf, NTHREADS);   // buffer full
        }
    }

    __syncthreads();

    // 2-way softmax + store. out shape (B, 2, T)
    if (tid < PAIRS) {
        float s1 = score[tid];
        float s2 = score[PAIRS + tid];
        float d  = s2 - s1;
        float a1 = 1.0f / (1.0f + __expf(d));
        float a2 = 1.0f / (1.0f + __expf(-d));
        int gp = pair0 + tid;
        int b  = gp >> 12;          // / T_
        int tt = gp & (T_ - 1);
        out[(size_t)b * (2 * T_) + tt]      = a1;
        out[(size_t)b * (2 * T_) + T_ + tt] = a2;
    }
}

extern "C" void kernel_launch(void* const* d_in, const int* in_sizes, int n_in,
                              void* d_out, int out_size) {
    const float* h1   = (const float*)d_in[0];
    const float* h2   = (const float*)d_in[1];
    const float* w_tp = (const float*)d_in[2];
    const float* v_tp = (const float*)d_in[3];
    float* out = (float*)d_out;

    cudaFuncSetAttribute(topo_attn_kernel,
                         cudaFuncAttributeMaxDynamicSharedMemorySize, SMEM_BYTES);

    int grid = (B_ * T_) / PAIRS;   // 2048
    topo_attn_kernel<<<grid, NTHREADS, SMEM_BYTES>>>(h1, h2, w_tp, v_tp, out);
}

// round 6
// speedup vs baseline: 2.3898x; 2.3898x over previous
#include <cuda_runtime.h>
#include <cuda_fp16.h>
#include <cstdint>

// Problem constants
#define B_  32
#define T_  4096
#define M_  256     // K dim of GEMM
#define L_  128     // hidden (N dim of GEMM)

#define PAIRS     128           // (b,t) pairs per CTA
#define ROWS      256           // MMA rows: h1 rows 0..127, h2 rows 128..255
#define NTHREADS  512           // 16 warps, each 16 rows x 128 cols
#define KCHUNK    32            // fp32 elems per k-chunk
#define NCHUNKS   8

#define HSTRIDE   40            // fp16 elems per H tile row (80B: 20-bank rotation)
#define VSTRIDE   264           // fp16 elems per V row (528B: 4-bank rotation; proven R3)

// smem byte offsets
#define SM_STAGE  0                         // 2 x (256 rows x 128 B) fp32 staging
#define STAGE_B   32768
#define SM_HH     65536                     // 256 x 40 fp16
#define SM_HL     86016
#define SM_V      106496                    // 128 x 264 fp16
#define SM_WS     174080                    // 128 floats
#define SM_SCORE  174592                    // 256 floats
#define SMEM_BYTES 175616

__device__ __half g_Vh[L_ * M_];

__device__ __forceinline__ float fast_tanh(float x) {
    float e = __expf(2.0f * x);
    return 1.0f - __fdividef(2.0f, e + 1.0f);
}

__device__ __forceinline__ void split2h(float a, float b, uint32_t& hi, uint32_t& lo) {
    __half ah = __float2half_rn(a);
    __half bh = __float2half_rn(b);
    __half2 hv; hv.x = ah; hv.y = bh;
    hi = *reinterpret_cast<uint32_t*>(&hv);
    __half2 lv;
    lv.x = __float2half_rn(a - __half2float(ah));
    lv.y = __float2half_rn(b - __half2float(bh));
    lo = *reinterpret_cast<uint32_t*>(&lv);
}

__device__ __forceinline__ void mma_f16(float* c, const uint32_t* a,
                                        uint32_t b0, uint32_t b1) {
    asm("mma.sync.aligned.m16n8k16.row.col.f32.f16.f16.f32 "
        "{%0,%1,%2,%3}, {%4,%5,%6,%7}, {%8,%9}, {%0,%1,%2,%3};\n"
        : "+f"(c[0]), "+f"(c[1]), "+f"(c[2]), "+f"(c[3])
        : "r"(a[0]), "r"(a[1]), "r"(a[2]), "r"(a[3]), "r"(b0), "r"(b1));
}

__device__ __forceinline__ void ldsm4(uint32_t& r0, uint32_t& r1, uint32_t& r2, uint32_t& r3,
                                      uint32_t addr) {
    asm volatile("ldmatrix.sync.aligned.m8n8.x4.shared.b16 {%0,%1,%2,%3}, [%4];\n"
                 : "=r"(r0), "=r"(r1), "=r"(r2), "=r"(r3) : "r"(addr));
}

__device__ __forceinline__ void cp16(uint32_t dst, const void* src) {
    asm volatile("cp.async.cg.shared.global [%0], [%1], 16;\n"
                 :: "r"(dst), "l"(src) : "memory");
}
#define CP_COMMIT() asm volatile("cp.async.commit_group;\n" ::: "memory")
#define CP_WAIT(n)  asm volatile("cp.async.wait_group %0;\n" :: "n"(n) : "memory")

// ---------------- kernel 1: round V to fp16 ----------------
__global__ void vprep_kernel(const float* __restrict__ v_tp) {
    int i = blockIdx.x * blockDim.x + threadIdx.x;
    if (i < L_ * M_) g_Vh[i] = __float2half_rn(v_tp[i]);
}

// ---------------- kernel 2: main ----------------
extern __shared__ char smem[];

__global__ void __launch_bounds__(NTHREADS, 1)
topo_attn_kernel(const float* __restrict__ h1, const float* __restrict__ h2,
                 const float* __restrict__ w_tp, float* __restrict__ out)
{
    uint32_t sb;
    asm("{ .reg .u64 t; cvta.to.shared.u64 t, %1; cvt.u32.u64 %0, t; }"
        : "=r"(sb) : "l"(smem));

    const int tid  = threadIdx.x;
    const int warp = tid >> 5;
    const int lane = tid & 31;
    const int pair0 = blockIdx.x * PAIRS;

    float* ws    = reinterpret_cast<float*>(smem + SM_WS);
    float* score = reinterpret_cast<float*>(smem + SM_SCORE);

    // ---- prologue: start cp.async of chunk 0, then copy V + w while it flies
    {
        const int r = tid >> 3;           // staging row (MMA row)
        const int c = tid & 7;            // 16B column
        const float* src0 = (r < PAIRS)
            ? (h1 + (size_t)(pair0 + r) * M_)
            : (h2 + (size_t)(pair0 + r - PAIRS) * M_);
        // 2048 16B chunks, 4 per thread (rows r, r+64, r+128, r+192)
        #pragma unroll
        for (int i = 0; i < 4; ++i) {
            int rr = r + i * 64;
            const float* src = (rr < PAIRS)
                ? (h1 + (size_t)(pair0 + rr) * M_)
                : (h2 + (size_t)(pair0 + rr - PAIRS) * M_);
            cp16(sb + SM_STAGE + rr * 128 + c * 16, src + c * 4);
        }
        CP_COMMIT();
        (void)src0;
    }
    if (tid < L_) ws[tid] = w_tp[tid];
    {
        // copy fp16 V into padded smem: 128 rows x 256 halves -> stride 264
        #pragma unroll
        for (int i = 0; i < 8; ++i) {
            int idx = i * NTHREADS + tid;      // uint4 idx over 128*32
            int r   = idx >> 5;
            int c8  = idx & 31;
            uint4 v = *reinterpret_cast<const uint4*>(g_Vh + r * M_ + c8 * 8);
            *reinterpret_cast<uint4*>(reinterpret_cast<__half*>(smem + SM_V) + r * VSTRIDE + c8 * 8) = v;
        }
    }

    // ldmatrix lane-address decomposition (R3-proven)
    const int rb   = warp * 16;
    const int arow = rb + (lane & 7) + ((lane >> 3) & 1) * 8;
    const int acol = (lane >> 4) * 8;
    const int brow = (lane & 7) + ((lane >> 4) & 1) * 8;
    const int bcol = ((lane >> 3) & 1) * 8;

    const uint32_t a_hh = sb + SM_HH + (arow * HSTRIDE + acol) * 2;
    const uint32_t a_hl = sb + SM_HL + (arow * HSTRIDE + acol) * 2;
    const uint32_t b_v0 = sb + SM_V  + (brow * VSTRIDE + bcol) * 2;

    float acc[16][4];
    #pragma unroll
    for (int n = 0; n < 16; ++n)
        #pragma unroll
        for (int q = 0; q < 4; ++q) acc[n][q] = 0.0f;

    for (int kc = 0; kc < NCHUNKS; ++kc) {
        const int buf = kc & 1;
        // issue next chunk's loads
        if (kc + 1 < NCHUNKS) {
            const int nb = (kc + 1) & 1;
            const int c = tid & 7;
            #pragma unroll
            for (int i = 0; i < 4; ++i) {
                int rr = (tid >> 3) + i * 64;
                const float* src = (rr < PAIRS)
                    ? (h1 + (size_t)(pair0 + rr) * M_)
                    : (h2 + (size_t)(pair0 + rr - PAIRS) * M_);
                cp16(sb + SM_STAGE + nb * STAGE_B + rr * 128 + c * 16,
                     src + (kc + 1) * KCHUNK + c * 4);
            }
            CP_COMMIT();
            CP_WAIT(1);
        } else {
            CP_WAIT(0);
        }
        __syncthreads();   // chunk kc staged; previous mma done with tiles

        // ---- split fp32 staging -> fp16 hi/lo tiles
        {
            const float* stg = reinterpret_cast<const float*>(smem + SM_STAGE + buf * STAGE_B);
            __half* hh = reinterpret_cast<__half*>(smem + SM_HH);
            __half* hl = reinterpret_cast<__half*>(smem + SM_HL);
            #pragma unroll
            for (int i = 0; i < 4; ++i) {
                int idx = i * NTHREADS + tid;     // float4 idx over 256*8
                int r   = idx >> 3;
                int c4  = idx & 7;
                float4 f = *reinterpret_cast<const float4*>(stg + r * 32 + c4 * 4);
                uint2 hv, lv;
                split2h(f.x, f.y, hv.x, lv.x);
                split2h(f.z, f.w, hv.y, lv.y);
                *reinterpret_cast<uint2*>(hh + r * HSTRIDE + c4 * 4) = hv;
                *reinterpret_cast<uint2*>(hl + r * HSTRIDE + c4 * 4) = lv;
            }
        }
        __syncthreads();

        // ---- mma over this chunk: 2 ksteps of k16
        #pragma unroll
        for (int ks = 0; ks < KCHUNK / 16; ++ks) {
            const int kk = ks * 16;
            uint32_t ah[4], al[4];
            ldsm4(ah[0], ah[1], ah[2], ah[3], a_hh + kk * 2);
            ldsm4(al[0], al[1], al[2], al[3], a_hl + kk * 2);
            const uint32_t kb = (kc * KCHUNK + kk) * 2;
            #pragma unroll
            for (int p = 0; p < 8; ++p) {
                uint32_t b0, b1, b2, b3;
                ldsm4(b0, b1, b2, b3, b_v0 + p * (16 * VSTRIDE * 2) + kb);
                mma_f16(acc[2 * p],     ah, b0, b1);
                mma_f16(acc[2 * p],     al, b0, b1);
                mma_f16(acc[2 * p + 1], ah, b2, b3);
                mma_f16(acc[2 * p + 1], al, b2, b3);
            }
        }
    }

    // ---- epilogue: score[row] = sum_l w[l] * tanh(temp[row,l])
    {
        const int g = lane >> 2;
        const int t = lane & 3;
        float p0 = 0.f, p1 = 0.f;
        #pragma unroll
        for (int nt = 0; nt < 16; ++nt) {
            float w0 = ws[nt * 8 + 2 * t];
            float w1 = ws[nt * 8 + 2 * t + 1];
            p0 += w0 * fast_tanh(acc[nt][0]) + w1 * fast_tanh(acc[nt][1]);
            p1 += w0 * fast_tanh(acc[nt][2]) + w1 * fast_tanh(acc[nt][3]);
        }
        #pragma unroll
        for (int off = 1; off < 4; off <<= 1) {
            p0 += __shfl_xor_sync(0xffffffffu, p0, off);
            p1 += __shfl_xor_sync(0xffffffffu, p1, off);
        }
        if (t == 0) {
            score[rb + g]     = p0;
            score[rb + g + 8] = p1;
        }
    }
    __syncthreads();

    // ---- 2-way softmax + store. out shape (B, 2, T)
    if (tid < PAIRS) {
        float s1 = score[tid];
        float s2 = score[PAIRS + tid];
        float d  = s2 - s1;
        float a1 = 1.0f / (1.0f + __expf(d));
        float a2 = 1.0f / (1.0f + __expf(-d));
        int gp = pair0 + tid;
        int b  = gp >> 12;          // / T_
        int tt = gp & (T_ - 1);
        out[(size_t)b * (2 * T_) + tt]      = a1;
        out[(size_t)b * (2 * T_) + T_ + tt] = a2;
    }
}

extern "C" void kernel_launch(void* const* d_in, const int* in_sizes, int n_in,
                              void* d_out, int out_size) {
    const float* h1   = (const float*)d_in[0];
    const float* h2   = (const float*)d_in[1];
    const float* w_tp = (const float*)d_in[2];
    const float* v_tp = (const float*)d_in[3];
    float* out = (float*)d_out;

    cudaFuncSetAttribute(topo_attn_kernel,
                         cudaFuncAttributeMaxDynamicSharedMemorySize, SMEM_BYTES);

    vprep_kernel<<<(L_ * M_ + 255) / 256, 256>>>(v_tp);

    int grid = (B_ * T_) / PAIRS;   // 1024
    topo_attn_kernel<<<grid, NTHREADS, SMEM_BYTES>>>(h1, h2, w_tp, out);
}

// round 7
// speedup vs baseline: 3.4746x; 1.4539x over previous
#include <cuda_runtime.h>
#include <cuda_fp16.h>
#include <cstdint>

// Problem constants
#define B_  32
#define T_  4096
#define M_  256     // K dim of GEMM
#define L_  128     // hidden (N dim of GEMM)

#define PAIRS     64            // (b,t) pairs per CTA
#define ROWS      128           // MMA rows: h1 rows 0..63, h2 rows 64..127
#define NTHREADS  256           // 8 warps, each 16 rows x 128 cols
#define KCHUNK    32            // fp32 elems per k-chunk
#define NCHUNKS   8

#define HSTRIDE   40            // fp16 elems per H tile row (80B: conflict-free ldsm, proven R5)
#define VSTRIDE   264           // fp16 elems per V row (528B; proven R3/R5)

// smem byte offsets
#define SM_H      0                          // 128 x 40 fp16 = 10240 B (single buffer)
#define SM_V      10240                      // 128 x 264 fp16 = 67584 B
#define SM_WS     77824                      // 128 floats
#define SM_SCORE  78336                      // 128 floats
#define SMEM_BYTES 78848

__device__ __half g_Vh[L_ * M_];

__device__ __forceinline__ float fast_tanh(float x) {
    float e = __expf(2.0f * x);
    return 1.0f - __fdividef(2.0f, e + 1.0f);
}

__device__ __forceinline__ uint32_t pack2h(float a, float b) {
    __half2 hv; hv.x = __float2half_rn(a); hv.y = __float2half_rn(b);
    return *reinterpret_cast<uint32_t*>(&hv);
}

__device__ __forceinline__ void mma_f16(float* c, const uint32_t* a,
                                        uint32_t b0, uint32_t b1) {
    asm("mma.sync.aligned.m16n8k16.row.col.f32.f16.f16.f32 "
        "{%0,%1,%2,%3}, {%4,%5,%6,%7}, {%8,%9}, {%0,%1,%2,%3};\n"
        : "+f"(c[0]), "+f"(c[1]), "+f"(c[2]), "+f"(c[3])
        : "r"(a[0]), "r"(a[1]), "r"(a[2]), "r"(a[3]), "r"(b0), "r"(b1));
}

__device__ __forceinline__ void ldsm4(uint32_t& r0, uint32_t& r1, uint32_t& r2, uint32_t& r3,
                                      uint32_t addr) {
    asm volatile("ldmatrix.sync.aligned.m8n8.x4.shared.b16 {%0,%1,%2,%3}, [%4];\n"
                 : "=r"(r0), "=r"(r1), "=r"(r2), "=r"(r3) : "r"(addr));
}

// ---------------- kernel 1: round V to fp16 ----------------
__global__ void vprep_kernel(const float* __restrict__ v_tp) {
    int i = blockIdx.x * blockDim.x + threadIdx.x;
    if (i < L_ * M_) g_Vh[i] = __float2half_rn(v_tp[i]);
}

// ---------------- kernel 2: main ----------------
extern __shared__ char smem[];

__global__ void __launch_bounds__(NTHREADS, 2)
topo_attn_kernel(const float* __restrict__ h1, const float* __restrict__ h2,
                 const float* __restrict__ w_tp, float* __restrict__ out)
{
    uint32_t sb;
    asm("{ .reg .u64 t; cvta.to.shared.u64 t, %1; cvt.u32.u64 %0, t; }"
        : "=r"(sb) : "l"(smem));

    const int tid  = threadIdx.x;
    const int warp = tid >> 5;
    const int lane = tid & 31;
    const int pair0 = blockIdx.x * PAIRS;

    float* ws    = reinterpret_cast<float*>(smem + SM_WS);
    float* score = reinterpret_cast<float*>(smem + SM_SCORE);
    __half* Hs   = reinterpret_cast<__half*>(smem + SM_H);
    __half* Vs   = reinterpret_cast<__half*>(smem + SM_V);

    // per-thread H staging coords: 4 float4 per chunk over (128 rows x 8 c4)
    const int hr  = tid >> 3;          // 0..31 (+32*i)
    const int hc4 = tid & 7;

    const float* hsrc[4];
    #pragma unroll
    for (int i = 0; i < 4; ++i) {
        int rr = hr + i * 32;
        hsrc[i] = (rr < PAIRS)
            ? (h1 + (size_t)(pair0 + rr) * M_)
            : (h2 + (size_t)(pair0 + rr - PAIRS) * M_);
    }

    // ---- issue chunk-0 LDGs immediately
    float4 f[4];
    #pragma unroll
    for (int i = 0; i < 4; ++i)
        f[i] = *reinterpret_cast<const float4*>(hsrc[i] + hc4 * 4);

    // ---- while they fly: copy V (fp16, L2-resident) and w into smem
    if (tid < L_) ws[tid] = w_tp[tid];
    #pragma unroll
    for (int i = 0; i < 16; ++i) {
        int idx = i * NTHREADS + tid;      // uint4 idx over 128*32
        int r   = idx >> 5;
        int c8  = idx & 31;
        uint4 v = *reinterpret_cast<const uint4*>(g_Vh + r * M_ + c8 * 8);
        *reinterpret_cast<uint4*>(Vs + r * VSTRIDE + c8 * 8) = v;
    }

    // ldmatrix lane-address decomposition (proven R3/R5)
    const int rb   = warp * 16;
    const int arow = rb + (lane & 7) + ((lane >> 3) & 1) * 8;
    const int acol = (lane >> 4) * 8;
    const int brow = (lane & 7) + ((lane >> 4) & 1) * 8;
    const int bcol = ((lane >> 3) & 1) * 8;

    const uint32_t a_h0 = sb + SM_H + (arow * HSTRIDE + acol) * 2;
    const uint32_t b_v0 = sb + SM_V + (brow * VSTRIDE + bcol) * 2;

    float acc[16][4];
    #pragma unroll
    for (int n = 0; n < 16; ++n)
        #pragma unroll
        for (int q = 0; q < 4; ++q) acc[n][q] = 0.0f;

    for (int kc = 0; kc < NCHUNKS; ++kc) {
        __syncthreads();   // previous mma done reading Hs (and V copy done at kc=0)

        // ---- cvt + store chunk kc to smem (no split: pure fp16)
        #pragma unroll
        for (int i = 0; i < 4; ++i) {
            uint2 hv;
            hv.x = pack2h(f[i].x, f[i].y);
            hv.y = pack2h(f[i].z, f[i].w);
            *reinterpret_cast<uint2*>(Hs + (hr + i * 32) * HSTRIDE + hc4 * 4) = hv;
        }
        __syncthreads();

        // ---- issue next chunk's LDGs (fly under the mma below)
        if (kc + 1 < NCHUNKS) {
            #pragma unroll
            for (int i = 0; i < 4; ++i)
                f[i] = *reinterpret_cast<const float4*>(hsrc[i] + (kc + 1) * KCHUNK + hc4 * 4);
        }

        // ---- mma over this chunk: 2 ksteps of k16
        #pragma unroll
        for (int ks = 0; ks < 2; ++ks) {
            const int kk = ks * 16;
            uint32_t a[4];
            ldsm4(a[0], a[1], a[2], a[3], a_h0 + kk * 2);
            const uint32_t kb = (kc * KCHUNK + kk) * 2;
            #pragma unroll
            for (int p = 0; p < 8; ++p) {
                uint32_t b0, b1, b2, b3;
                ldsm4(b0, b1, b2, b3, b_v0 + p * (16 * VSTRIDE * 2) + kb);
                mma_f16(acc[2 * p],     a, b0, b1);
                mma_f16(acc[2 * p + 1], a, b2, b3);
            }
        }
    }

    // ---- epilogue: score[row] = sum_l w[l] * tanh(temp[row,l])
    {
        const int g = lane >> 2;
        const int t = lane & 3;
        float p0 = 0.f, p1 = 0.f;
        #pragma unroll
        for (int nt = 0; nt < 16; ++nt) {
            float w0 = ws[nt * 8 + 2 * t];
            float w1 = ws[nt * 8 + 2 * t + 1];
            p0 += w0 * fast_tanh(acc[nt][0]) + w1 * fast_tanh(acc[nt][1]);
            p1 += w0 * fast_tanh(acc[nt][2]) + w1 * fast_tanh(acc[nt][3]);
        }
        #pragma unroll
        for (int off = 1; off < 4; off <<= 1) {
            p0 += __shfl_xor_sync(0xffffffffu, p0, off);
            p1 += __shfl_xor_sync(0xffffffffu, p1, off);
        }
        if (t == 0) {
            score[rb + g]     = p0;
            score[rb + g + 8] = p1;
        }
    }
    __syncthreads();

    // ---- 2-way softmax + store. out shape (B, 2, T)
    if (tid < PAIRS) {
        float s1 = score[tid];
        float s2 = score[PAIRS + tid];
        float d  = s2 - s1;
        float a1 = 1.0f / (1.0f + __expf(d));
        float a2 = 1.0f / (1.0f + __expf(-d));
        int gp = pair0 + tid;
        int b  = gp >> 12;          // / T_
        int tt = gp & (T_ - 1);
        out[(size_t)b * (2 * T_) + tt]      = a1;
        out[(size_t)b * (2 * T_) + T_ + tt] = a2;
    }
}

extern "C" void kernel_launch(void* const* d_in, const int* in_sizes, int n_in,
                              void* d_out, int out_size) {
    const float* h1   = (const float*)d_in[0];
    const float* h2   = (const float*)d_in[1];
    const float* w_tp = (const float*)d_in[2];
    const float* v_tp = (const float*)d_in[3];
    float* out = (float*)d_out;

    cudaFuncSetAttribute(topo_attn_kernel,
                         cudaFuncAttributeMaxDynamicSharedMemorySize, SMEM_BYTES);

    vprep_kernel<<<(L_ * M_ + 255) / 256, 256>>>(v_tp);

    int grid = (B_ * T_) / PAIRS;   // 2048
    topo_attn_kernel<<<grid, NTHREADS, SMEM_BYTES>>>(h1, h2, w_tp, out);
}

// round 8
// speedup vs baseline: 3.8383x; 1.1047x over previous
#include <cuda_runtime.h>
#include <cuda_fp16.h>
#include <cstdint>

// Problem constants
#define B_  32
#define T_  4096
#define M_  256     // K dim of GEMM
#define L_  128     // hidden (N dim of GEMM)

#define PAIRS     64            // (b,t) pairs per CTA
#define ROWS      128           // MMA rows: h1 rows 0..63, h2 rows 64..127
#define NTHREADS  256           // 8 warps: grid (4 row-groups x 2 col-halves)
#define KCHUNK    32            // fp32 elems per k-chunk
#define NCHUNKS   8

#define HSTRIDE   40            // fp16 elems per H tile row (80B; proven conflict-free)
#define VSTRIDE   264           // fp16 elems per V row (528B; proven)

// smem byte offsets
#define SM_H      0                          // 128 x 40 fp16 = 10240 B
#define SM_V      10240                      // 128 x 264 fp16 = 67584 B
#define SM_WS     77824                      // 128 floats
#define SM_SCORE  78336                      // 2 x 128 floats (per column-half)
#define SMEM_BYTES 79360

__device__ __half g_Vh[L_ * M_];

__device__ __forceinline__ float fast_tanh(float x) {
    float e = __expf(2.0f * x);
    return 1.0f - __fdividef(2.0f, e + 1.0f);
}

__device__ __forceinline__ uint32_t pack2h(float a, float b) {
    __half2 hv; hv.x = __float2half_rn(a); hv.y = __float2half_rn(b);
    return *reinterpret_cast<uint32_t*>(&hv);
}

__device__ __forceinline__ void mma_f16(float* c, const uint32_t* a,
                                        uint32_t b0, uint32_t b1) {
    asm("mma.sync.aligned.m16n8k16.row.col.f32.f16.f16.f32 "
        "{%0,%1,%2,%3}, {%4,%5,%6,%7}, {%8,%9}, {%0,%1,%2,%3};\n"
        : "+f"(c[0]), "+f"(c[1]), "+f"(c[2]), "+f"(c[3])
        : "r"(a[0]), "r"(a[1]), "r"(a[2]), "r"(a[3]), "r"(b0), "r"(b1));
}

__device__ __forceinline__ void ldsm4(uint32_t& r0, uint32_t& r1, uint32_t& r2, uint32_t& r3,
                                      uint32_t addr) {
    asm volatile("ldmatrix.sync.aligned.m8n8.x4.shared.b16 {%0,%1,%2,%3}, [%4];\n"
                 : "=r"(r0), "=r"(r1), "=r"(r2), "=r"(r3) : "r"(addr));
}

// ---------------- kernel 1: round V to fp16 ----------------
__global__ void vprep_kernel(const float* __restrict__ v_tp) {
    int i = blockIdx.x * blockDim.x + threadIdx.x;
    if (i < L_ * M_) g_Vh[i] = __float2half_rn(v_tp[i]);
}

// ---------------- kernel 2: main ----------------
extern __shared__ char smem[];

__global__ void __launch_bounds__(NTHREADS, 2)
topo_attn_kernel(const float* __restrict__ h1, const float* __restrict__ h2,
                 const float* __restrict__ w_tp, float* __restrict__ out)
{
    uint32_t sb;
    asm("{ .reg .u64 t; cvta.to.shared.u64 t, %1; cvt.u32.u64 %0, t; }"
        : "=r"(sb) : "l"(smem));

    const int tid  = threadIdx.x;
    const int warp = tid >> 5;
    const int lane = tid & 31;
    const int pair0 = blockIdx.x * PAIRS;

    float* ws     = reinterpret_cast<float*>(smem + SM_WS);
    float* scoreA = reinterpret_cast<float*>(smem + SM_SCORE);          // col half 0
    float* scoreB = scoreA + 128;                                       // col half 1
    __half* Hs    = reinterpret_cast<__half*>(smem + SM_H);
    __half* Vs    = reinterpret_cast<__half*>(smem + SM_V);

    // per-thread H staging coords: 4 float4 per chunk over (128 rows x 8 c4)
    const int hr  = tid >> 3;          // 0..31 (+32*i)
    const int hc4 = tid & 7;

    const float* hsrc[4];
    #pragma unroll
    for (int i = 0; i < 4; ++i) {
        int rr = hr + i * 32;
        hsrc[i] = (rr < PAIRS)
            ? (h1 + (size_t)(pair0 + rr) * M_)
            : (h2 + (size_t)(pair0 + rr - PAIRS) * M_);
    }

    // ---- issue chunk-0 LDGs immediately
    float4 f[4];
    #pragma unroll
    for (int i = 0; i < 4; ++i)
        f[i] = *reinterpret_cast<const float4*>(hsrc[i] + hc4 * 4);

    // ---- while they fly: copy V (fp16, L2/L1-resident) and w into smem
    if (tid < L_) ws[tid] = w_tp[tid];
    #pragma unroll
    for (int i = 0; i < 16; ++i) {
        int idx = i * NTHREADS + tid;      // uint4 idx over 128*32
        int r   = idx >> 5;
        int c8  = idx & 31;
        uint4 v = *reinterpret_cast<const uint4*>(g_Vh + r * M_ + c8 * 8);
        *reinterpret_cast<uint4*>(Vs + r * VSTRIDE + c8 * 8) = v;
    }

    // warp tiling: 4 row-groups x 2 col-halves
    const int wr = warp >> 1;          // 0..3 -> rows wr*32 .. wr*32+31
    const int wc = warp & 1;           // 0..1 -> cols wc*64 .. wc*64+63
    const int rb = wr * 32;
    const int cb = wc * 64;

    // ldmatrix lane-address decomposition (within a 16-row / 16-col tile)
    const int arow = (lane & 7) + ((lane >> 3) & 1) * 8;
    const int acol = (lane >> 4) * 8;
    const int brow = (lane & 7) + ((lane >> 4) & 1) * 8;
    const int bcol = ((lane >> 3) & 1) * 8;

    const uint32_t a_h0 = sb + SM_H + ((rb + arow) * HSTRIDE + acol) * 2;
    const uint32_t b_v0 = sb + SM_V + ((cb + brow) * VSTRIDE + bcol) * 2;

    float acc[2][8][4];                // [row-tile m16][col-tile n8][frag]
    #pragma unroll
    for (int rt = 0; rt < 2; ++rt)
        #pragma unroll
        for (int n = 0; n < 8; ++n)
            #pragma unroll
            for (int q = 0; q < 4; ++q) acc[rt][n][q] = 0.0f;

    for (int kc = 0; kc < NCHUNKS; ++kc) {
        __syncthreads();   // previous mma done reading Hs (and V copy done at kc=0)

        // ---- cvt + store chunk kc to smem (pure fp16)
        #pragma unroll
        for (int i = 0; i < 4; ++i) {
            uint2 hv;
            hv.x = pack2h(f[i].x, f[i].y);
            hv.y = pack2h(f[i].z, f[i].w);
            *reinterpret_cast<uint2*>(Hs + (hr + i * 32) * HSTRIDE + hc4 * 4) = hv;
        }
        __syncthreads();

        // ---- issue next chunk's LDGs (fly under the mma below)
        if (kc + 1 < NCHUNKS) {
            #pragma unroll
            for (int i = 0; i < 4; ++i)
                f[i] = *reinterpret_cast<const float4*>(hsrc[i] + (kc + 1) * KCHUNK + hc4 * 4);
        }

        // ---- mma over this chunk: 2 ksteps of k16
        #pragma unroll
        for (int ks = 0; ks < 2; ++ks) {
            const int kk = ks * 16;
            uint32_t a0[4], a1[4];
            ldsm4(a0[0], a0[1], a0[2], a0[3], a_h0 + kk * 2);
            ldsm4(a1[0], a1[1], a1[2], a1[3], a_h0 + kk * 2 + 16 * HSTRIDE * 2);
            const uint32_t kb = (kc * KCHUNK + kk) * 2;
            #pragma unroll
            for (int p = 0; p < 4; ++p) {
                uint32_t b0, b1, b2, b3;
                ldsm4(b0, b1, b2, b3, b_v0 + p * (16 * VSTRIDE * 2) + kb);
                mma_f16(acc[0][2 * p],     a0, b0, b1);
                mma_f16(acc[0][2 * p + 1], a0, b2, b3);
                mma_f16(acc[1][2 * p],     a1, b0, b1);
                mma_f16(acc[1][2 * p + 1], a1, b2, b3);
            }
        }
    }

    // ---- epilogue: partial score over this warp's 64 columns
    {
        const int g = lane >> 2;
        const int t = lane & 3;
        float p0[2], p1[2];             // [row-tile] rows g / g+8
        #pragma unroll
        for (int rt = 0; rt < 2; ++rt) { p0[rt] = 0.f; p1[rt] = 0.f; }
        #pragma unroll
        for (int nt = 0; nt < 8; ++nt) {
            float w0 = ws[cb + nt * 8 + 2 * t];
            float w1 = ws[cb + nt * 8 + 2 * t + 1];
            #pragma unroll
            for (int rt = 0; rt < 2; ++rt) {
                p0[rt] += w0 * fast_tanh(acc[rt][nt][0]) + w1 * fast_tanh(acc[rt][nt][1]);
                p1[rt] += w0 * fast_tanh(acc[rt][nt][2]) + w1 * fast_tanh(acc[rt][nt][3]);
            }
        }
        #pragma unroll
        for (int off = 1; off < 4; off <<= 1) {
            #pragma unroll
            for (int rt = 0; rt < 2; ++rt) {
                p0[rt] += __shfl_xor_sync(0xffffffffu, p0[rt], off);
                p1[rt] += __shfl_xor_sync(0xffffffffu, p1[rt], off);
            }
        }
        if (t == 0) {
            float* sc = wc ? scoreB : scoreA;
            #pragma unroll
            for (int rt = 0; rt < 2; ++rt) {
                sc[rb + rt * 16 + g]     = p0[rt];
                sc[rb + rt * 16 + g + 8] = p1[rt];
            }
        }
    }
    __syncthreads();

    // ---- 2-way softmax + store. out shape (B, 2, T)
    if (tid < PAIRS) {
        float s1 = scoreA[tid]         + scoreB[tid];
        float s2 = scoreA[PAIRS + tid] + scoreB[PAIRS + tid];
        float d  = s2 - s1;
        float a1 = 1.0f / (1.0f + __expf(d));
        float a2 = 1.0f / (1.0f + __expf(-d));
        int gp = pair0 + tid;
        int b  = gp >> 12;          // / T_
        int tt = gp & (T_ - 1);
        out[(size_t)b * (2 * T_) + tt]      = a1;
        out[(size_t)b * (2 * T_) + T_ + tt] = a2;
    }
}

extern "C" void kernel_launch(void* const* d_in, const int* in_sizes, int n_in,
                              void* d_out, int out_size) {
    const float* h1   = (const float*)d_in[0];
    const float* h2   = (const float*)d_in[1];
    const float* w_tp = (const float*)d_in[2];
    const float* v_tp = (const float*)d_in[3];
    float* out = (float*)d_out;

    cudaFuncSetAttribute(topo_attn_kernel,
                         cudaFuncAttributeMaxDynamicSharedMemorySize, SMEM_BYTES);

    vprep_kernel<<<(L_ * M_ + 255) / 256, 256>>>(v_tp);

    int grid = (B_ * T_) / PAIRS;   // 2048
    topo_attn_kernel<<<grid, NTHREADS, SMEM_BYTES>>>(h1, h2, w_tp, out);
}

// round 9
// speedup vs baseline: 3.9526x; 1.0298x over previous
#include <cuda_runtime.h>
#include <cuda_fp16.h>
#include <cstdint>

// Problem constants
#define B_  32
#define T_  4096
#define M_  256     // K dim of GEMM
#define L_  128     // hidden (N dim of GEMM)

#define PAIRS     64            // (b,t) pairs per CTA
#define ROWS      128           // MMA rows: h1 rows 0..63, h2 rows 64..127
#define NTHREADS  256           // 8 warps: grid (4 row-groups x 2 col-halves)
#define KCHUNK    32            // fp32 elems per k-chunk
#define NCHUNKS   8

#define HSTRIDE   40            // fp16 elems per H tile row (80B; proven conflict-free)
#define VSTRIDE   264           // fp16 elems per V row (528B; proven)

#define HBUF_B    (ROWS * HSTRIDE * 2)       // 10240 B per H buffer

// smem byte offsets
#define SM_H      0                          // 2 x 10240 B (double buffer)
#define SM_V      20480                      // 128 x 264 fp16 = 67584 B
#define SM_WS     88064                      // 128 floats
#define SM_SCORE  88576                      // 2 x 128 floats (per column-half)
#define SMEM_BYTES 89600

__device__ __half g_Vh[L_ * M_];

__device__ __forceinline__ float fast_tanh(float x) {
    float e = __expf(2.0f * x);
    return 1.0f - __fdividef(2.0f, e + 1.0f);
}

__device__ __forceinline__ uint32_t pack2h(float a, float b) {
    __half2 hv; hv.x = __float2half_rn(a); hv.y = __float2half_rn(b);
    return *reinterpret_cast<uint32_t*>(&hv);
}

__device__ __forceinline__ void mma_f16(float* c, const uint32_t* a,
                                        uint32_t b0, uint32_t b1) {
    asm("mma.sync.aligned.m16n8k16.row.col.f32.f16.f16.f32 "
        "{%0,%1,%2,%3}, {%4,%5,%6,%7}, {%8,%9}, {%0,%1,%2,%3};\n"
        : "+f"(c[0]), "+f"(c[1]), "+f"(c[2]), "+f"(c[3])
        : "r"(a[0]), "r"(a[1]), "r"(a[2]), "r"(a[3]), "r"(b0), "r"(b1));
}

__device__ __forceinline__ void ldsm4(uint32_t& r0, uint32_t& r1, uint32_t& r2, uint32_t& r3,
                                      uint32_t addr) {
    asm volatile("ldmatrix.sync.aligned.m8n8.x4.shared.b16 {%0,%1,%2,%3}, [%4];\n"
                 : "=r"(r0), "=r"(r1), "=r"(r2), "=r"(r3) : "r"(addr));
}

// ---------------- kernel 1: round V to fp16 ----------------
__global__ void vprep_kernel(const float* __restrict__ v_tp) {
    int i = blockIdx.x * blockDim.x + threadIdx.x;
    if (i < L_ * M_) g_Vh[i] = __float2half_rn(v_tp[i]);
}

// ---------------- kernel 2: main ----------------
extern __shared__ char smem[];

__global__ void __launch_bounds__(NTHREADS, 2)
topo_attn_kernel(const float* __restrict__ h1, const float* __restrict__ h2,
                 const float* __restrict__ w_tp, float* __restrict__ out)
{
    uint32_t sb;
    asm("{ .reg .u64 t; cvta.to.shared.u64 t, %1; cvt.u32.u64 %0, t; }"
        : "=r"(sb) : "l"(smem));

    const int tid  = threadIdx.x;
    const int warp = tid >> 5;
    const int lane = tid & 31;
    const int pair0 = blockIdx.x * PAIRS;

    float* ws     = reinterpret_cast<float*>(smem + SM_WS);
    float* scoreA = reinterpret_cast<float*>(smem + SM_SCORE);          // col half 0
    float* scoreB = scoreA + 128;                                       // col half 1
    __half* Vs    = reinterpret_cast<__half*>(smem + SM_V);

    // per-thread H staging coords: 4 float4 per chunk over (128 rows x 8 c4)
    const int hr  = tid >> 3;          // 0..31 (+32*i)
    const int hc4 = tid & 7;

    const float* hsrc[4];
    #pragma unroll
    for (int i = 0; i < 4; ++i) {
        int rr = hr + i * 32;
        hsrc[i] = (rr < PAIRS)
            ? (h1 + (size_t)(pair0 + rr) * M_)
            : (h2 + (size_t)(pair0 + rr - PAIRS) * M_);
    }

    // ---- issue chunk-0 LDGs immediately
    float4 f[4];
    #pragma unroll
    for (int i = 0; i < 4; ++i)
        f[i] = *reinterpret_cast<const float4*>(hsrc[i] + hc4 * 4);

    // ---- while they fly: copy V (fp16, L2-resident) and w into smem
    if (tid < L_) ws[tid] = w_tp[tid];
    #pragma unroll
    for (int i = 0; i < 16; ++i) {
        int idx = i * NTHREADS + tid;      // uint4 idx over 128*32
        int r   = idx >> 5;
        int c8  = idx & 31;
        uint4 v = *reinterpret_cast<const uint4*>(g_Vh + r * M_ + c8 * 8);
        *reinterpret_cast<uint4*>(Vs + r * VSTRIDE + c8 * 8) = v;
    }

    // warp tiling: 4 row-groups x 2 col-halves
    const int wr = warp >> 1;          // 0..3 -> rows wr*32 .. wr*32+31
    const int wc = warp & 1;           // 0..1 -> cols wc*64 .. wc*64+63
    const int rb = wr * 32;
    const int cb = wc * 64;

    // ldmatrix lane-address decomposition (within a 16-row / 16-col tile)
    const int arow = (lane & 7) + ((lane >> 3) & 1) * 8;
    const int acol = (lane >> 4) * 8;
    const int brow = (lane & 7) + ((lane >> 4) & 1) * 8;
    const int bcol = ((lane >> 3) & 1) * 8;

    const uint32_t a_h0 = sb + SM_H + ((rb + arow) * HSTRIDE + acol) * 2;
    const uint32_t b_v0 = sb + SM_V + ((cb + brow) * VSTRIDE + bcol) * 2;

    float acc[2][8][4];                // [row-tile m16][col-tile n8][frag]
    #pragma unroll
    for (int rt = 0; rt < 2; ++rt)
        #pragma unroll
        for (int n = 0; n < 8; ++n)
            #pragma unroll
            for (int q = 0; q < 4; ++q) acc[rt][n][q] = 0.0f;

    for (int kc = 0; kc < NCHUNKS; ++kc) {
        const int buf = kc & 1;

        // ---- cvt + store chunk kc into buf (other buffer may still be read by laggards)
        __half* Hs = reinterpret_cast<__half*>(smem + SM_H + buf * HBUF_B);
        #pragma unroll
        for (int i = 0; i < 4; ++i) {
            uint2 hv;
            hv.x = pack2h(f[i].x, f[i].y);
            hv.y = pack2h(f[i].z, f[i].w);
            *reinterpret_cast<uint2*>(Hs + (hr + i * 32) * HSTRIDE + hc4 * 4) = hv;
        }
        __syncthreads();   // buf[kc] ready; also proves all warps past mma(kc-2) -> buf reuse safe

        // ---- issue next chunk's LDGs (fly under the mma below)
        if (kc + 1 < NCHUNKS) {
            #pragma unroll
            for (int i = 0; i < 4; ++i)
                f[i] = *reinterpret_cast<const float4*>(hsrc[i] + (kc + 1) * KCHUNK + hc4 * 4);
        }

        // ---- mma over this chunk: 2 ksteps of k16
        const uint32_t a_hb = a_h0 + buf * HBUF_B;
        #pragma unroll
        for (int ks = 0; ks < 2; ++ks) {
            const int kk = ks * 16;
            uint32_t a0[4], a1[4];
            ldsm4(a0[0], a0[1], a0[2], a0[3], a_hb + kk * 2);
            ldsm4(a1[0], a1[1], a1[2], a1[3], a_hb + kk * 2 + 16 * HSTRIDE * 2);
            const uint32_t kb = (kc * KCHUNK + kk) * 2;
            #pragma unroll
            for (int p = 0; p < 4; ++p) {
                uint32_t b0, b1, b2, b3;
                ldsm4(b0, b1, b2, b3, b_v0 + p * (16 * VSTRIDE * 2) + kb);
                mma_f16(acc[0][2 * p],     a0, b0, b1);
                mma_f16(acc[0][2 * p + 1], a0, b2, b3);
                mma_f16(acc[1][2 * p],     a1, b0, b1);
                mma_f16(acc[1][2 * p + 1], a1, b2, b3);
            }
        }
    }

    // ---- epilogue: partial score over this warp's 64 columns
    {
        const int g = lane >> 2;
        const int t = lane & 3;
        float p0[2], p1[2];             // [row-tile] rows g / g+8
        #pragma unroll
        for (int rt = 0; rt < 2; ++rt) { p0[rt] = 0.f; p1[rt] = 0.f; }
        #pragma unroll
        for (int nt = 0; nt < 8; ++nt) {
            float w0 = ws[cb + nt * 8 + 2 * t];
            float w1 = ws[cb + nt * 8 + 2 * t + 1];
            #pragma unroll
            for (int rt = 0; rt < 2; ++rt) {
                p0[rt] += w0 * fast_tanh(acc[rt][nt][0]) + w1 * fast_tanh(acc[rt][nt][1]);
                p1[rt] += w0 * fast_tanh(acc[rt][nt][2]) + w1 * fast_tanh(acc[rt][nt][3]);
            }
        }
        #pragma unroll
        for (int off = 1; off < 4; off <<= 1) {
            #pragma unroll
            for (int rt = 0; rt < 2; ++rt) {
                p0[rt] += __shfl_xor_sync(0xffffffffu, p0[rt], off);
                p1[rt] += __shfl_xor_sync(0xffffffffu, p1[rt], off);
            }
        }
        if (t == 0) {
            float* sc = wc ? scoreB : scoreA;
            #pragma unroll
            for (int rt = 0; rt < 2; ++rt) {
                sc[rb + rt * 16 + g]     = p0[rt];
                sc[rb + rt * 16 + g + 8] = p1[rt];
            }
        }
    }
    __syncthreads();

    // ---- 2-way softmax + store. out shape (B, 2, T)
    if (tid < PAIRS) {
        float s1 = scoreA[tid]         + scoreB[tid];
        float s2 = scoreA[PAIRS + tid] + scoreB[PAIRS + tid];
        float d  = s2 - s1;
        float a1 = 1.0f / (1.0f + __expf(d));
        float a2 = 1.0f / (1.0f + __expf(-d));
        int gp = pair0 + tid;
        int b  = gp >> 12;          // / T_
        int tt = gp & (T_ - 1);
        out[(size_t)b * (2 * T_) + tt]      = a1;
        out[(size_t)b * (2 * T_) + T_ + tt] = a2;
    }
}

extern "C" void kernel_launch(void* const* d_in, const int* in_sizes, int n_in,
                              void* d_out, int out_size) {
    const float* h1   = (const float*)d_in[0];
    const float* h2   = (const float*)d_in[1];
    const float* w_tp = (const float*)d_in[2];
    const float* v_tp = (const float*)d_in[3];
    float* out = (float*)d_out;

    cudaFuncSetAttribute(topo_attn_kernel,
                         cudaFuncAttributeMaxDynamicSharedMemorySize, SMEM_BYTES);

    vprep_kernel<<<(L_ * M_ + 255) / 256, 256>>>(v_tp);

    int grid = (B_ * T_) / PAIRS;   // 2048
    topo_attn_kernel<<<grid, NTHREADS, SMEM_BYTES>>>(h1, h2, w_tp, out);
}